// round 2
// baseline (speedup 1.0000x reference)
#include <cuda_runtime.h>

#define NB 2
#define NSEQ 2048
#define NC 1024
#define NH 16
#define ND 64
#define ATT_SCALE 0.125f
#define PSTR 68   // padded row stride (floats) for smem tiles: 68 mod 32 != 0 per row step

// Scratch (device globals: the sanctioned alloc-free workaround). 5 x 16.8 MB.
__device__ float g_q[NB*NH*NSEQ*ND];
__device__ float g_a[NB*NH*NSEQ*ND];
__device__ float g_k[NB*NH*NSEQ*ND];
__device__ float g_v[NB*NH*NSEQ*ND];
__device__ float g_t[NB*NH*NSEQ*ND];

// ---------------------------------------------------------------------------
// Projection GEMM: O = X[4096 x 1024] @ W^T  (W row-major [outC x 1024]),
// epilogue scatters into head layout [B,H,N,D]. Each 64-col tile maps to
// exactly one head (64-aligned), so the destination base is uniform per CTA.
// kvMode==1: cols [0,1024) -> O0 (k), cols [1024,2048) -> O1 (v).
// ---------------------------------------------------------------------------
__global__ __launch_bounds__(256) void proj_kernel(
    const float* __restrict__ X, const float* __restrict__ W,
    float* __restrict__ O0, float* __restrict__ O1, int kvMode)
{
    __shared__ float Ast[16][68];   // k-major: Ast[k][row]
    __shared__ float Bst[16][68];   // k-major: Bst[k][col]

    const int tid = threadIdx.x;
    const int tx  = tid & 15;
    const int ty  = tid >> 4;
    const int col0 = blockIdx.x * 64;
    const int row0 = blockIdx.y * 64;

    const int rw = tid >> 2;          // 0..63
    const int kg = (tid & 3) << 2;    // 0,4,8,12
    const float* Xr = X + (size_t)(row0 + rw) * NC + kg;
    const float* Wr = W + (size_t)(col0 + rw) * NC + kg;

    float acc[4][4] = {};

    for (int kt = 0; kt < NC; kt += 16) {
        float4 xa = *(const float4*)(Xr + kt);
        float4 wb = *(const float4*)(Wr + kt);
        Ast[kg+0][rw] = xa.x; Ast[kg+1][rw] = xa.y;
        Ast[kg+2][rw] = xa.z; Ast[kg+3][rw] = xa.w;
        Bst[kg+0][rw] = wb.x; Bst[kg+1][rw] = wb.y;
        Bst[kg+2][rw] = wb.z; Bst[kg+3][rw] = wb.w;
        __syncthreads();

        #pragma unroll
        for (int kk = 0; kk < 16; ++kk) {
            float4 av = *(const float4*)&Ast[kk][ty*4];
            float4 bv = *(const float4*)&Bst[kk][tx*4];
            float ar[4] = {av.x, av.y, av.z, av.w};
            float br[4] = {bv.x, bv.y, bv.z, bv.w};
            #pragma unroll
            for (int i = 0; i < 4; ++i)
                #pragma unroll
                for (int j = 0; j < 4; ++j)
                    acc[i][j] = fmaf(ar[i], br[j], acc[i][j]);
        }
        __syncthreads();
    }

    // Head-scatter epilogue
    float* dst;
    int hh;
    if (!kvMode) { dst = O0; hh = col0 >> 6; }
    else {
        int s = col0 >> 10;             // 0 -> k, 1 -> v
        hh = (col0 >> 6) & (NH - 1);
        dst = s ? O1 : O0;
    }
    const int b  = row0 >> 11;          // row0 / NSEQ
    const int n0 = row0 & (NSEQ - 1);
    float* ob = dst + ((size_t)(b*NH + hh) * NSEQ + n0) * ND;

    #pragma unroll
    for (int i = 0; i < 4; ++i) {
        float4 r4 = make_float4(acc[i][0], acc[i][1], acc[i][2], acc[i][3]);
        *(float4*)&ob[(size_t)(ty*4 + i) * ND + tx*4] = r4;
    }
}

// ---------------------------------------------------------------------------
// Flash attention (fp32, online softmax).
//   O[bh, n, :] = softmax(Q[bh] K[bh]^T * ATT_SCALE) V[bh]
// Q,K,V are head-layout [BH, N, D] with D=64 contiguous.
// Output addressing is generic: base = O + b*oOffB + h*oOffH, row stride oRS,
// so pass 2 can write straight into [B,N,C] (d_out) without a transpose kernel.
// Block: 256 threads (16x16), 64-query x 64-key tiles.
// All smem tiles use row stride PSTR=68 where inter-row conflicts matter:
//   Qt/Kt (d-major) and Ps (row-major). Vs keeps stride 64 (its reads index
//   banks by tx*4 and are conflict-free; its rows are only read broadcast-wise).
// ---------------------------------------------------------------------------
__global__ __launch_bounds__(256) void flash_kernel(
    const float* __restrict__ Qg, const float* __restrict__ Kg,
    const float* __restrict__ Vg, float* __restrict__ Og,
    long long oOffB, long long oOffH, int oRS)
{
    extern __shared__ float sm[];
    float* Qt = sm;                   // [64][PSTR]  d-major: Qt[d*PSTR + r]
    float* Kt = Qt + 64*PSTR;         // [64][PSTR]  d-major: Kt[d*PSTR + c]
    float* Vs = Kt + 64*PSTR;         // [64][64]    c-major: Vs[c*64 + dcol]
    float* Ps = Vs + 64*64;           // [64][PSTR]  r-major: Ps[r*PSTR + c]

    const int tid = threadIdx.x;
    const int tx  = tid & 15;
    const int ty  = tid >> 4;
    const int bh  = blockIdx.y;
    const int b   = bh / NH;
    const int h   = bh % NH;
    const int q0  = blockIdx.x * 64;

    const float* Qb = Qg + (size_t)bh * NSEQ * ND + (size_t)q0 * ND;
    const float* Kb = Kg + (size_t)bh * NSEQ * ND;
    const float* Vb = Vg + (size_t)bh * NSEQ * ND;

    // Load Q tile transposed (d-major). 64x64 floats, 4 float4 per thread.
    #pragma unroll
    for (int it = 0; it < 4; ++it) {
        int idx = tid + it * 256;
        int n  = idx >> 4;
        int dg = (idx & 15) << 2;
        float4 v4 = *(const float4*)(Qb + (size_t)n * ND + dg);
        Qt[(dg+0)*PSTR + n] = v4.x; Qt[(dg+1)*PSTR + n] = v4.y;
        Qt[(dg+2)*PSTR + n] = v4.z; Qt[(dg+3)*PSTR + n] = v4.w;
    }

    float o[4][4] = {};
    float m[4], l[4];
    #pragma unroll
    for (int i = 0; i < 4; ++i) { m[i] = -1e30f; l[i] = 0.f; }

    for (int kt0 = 0; kt0 < NSEQ; kt0 += 64) {
        __syncthreads();   // previous PV done (and Q stores covered on iter 0)

        // Load K (transposed, d-major) and V (c-major) tiles.
        #pragma unroll
        for (int it = 0; it < 4; ++it) {
            int idx = tid + it * 256;
            int n  = idx >> 4;
            int dg = (idx & 15) << 2;
            float4 k4 = *(const float4*)(Kb + (size_t)(kt0 + n) * ND + dg);
            Kt[(dg+0)*PSTR + n] = k4.x; Kt[(dg+1)*PSTR + n] = k4.y;
            Kt[(dg+2)*PSTR + n] = k4.z; Kt[(dg+3)*PSTR + n] = k4.w;
            float4 v4 = *(const float4*)(Vb + (size_t)(kt0 + n) * ND + dg);
            *(float4*)&Vs[n*64 + dg] = v4;
        }
        __syncthreads();

        // S = Q K^T  (64x64x64), 4x4 per thread via outer products.
        float s[4][4] = {};
        #pragma unroll 8
        for (int d = 0; d < 64; ++d) {
            float4 qv = *(const float4*)&Qt[d*PSTR + ty*4];
            float4 kv = *(const float4*)&Kt[d*PSTR + tx*4];
            float qa[4] = {qv.x, qv.y, qv.z, qv.w};
            float kb[4] = {kv.x, kv.y, kv.z, kv.w};
            #pragma unroll
            for (int i = 0; i < 4; ++i)
                #pragma unroll
                for (int j = 0; j < 4; ++j)
                    s[i][j] = fmaf(qa[i], kb[j], s[i][j]);
        }

        // Online softmax (row reductions across the 16 tx lanes, width-16 shfl).
        #pragma unroll
        for (int i = 0; i < 4; ++i) {
            #pragma unroll
            for (int j = 0; j < 4; ++j) s[i][j] *= ATT_SCALE;
            float rm = fmaxf(fmaxf(s[i][0], s[i][1]), fmaxf(s[i][2], s[i][3]));
            #pragma unroll
            for (int off = 8; off > 0; off >>= 1)
                rm = fmaxf(rm, __shfl_xor_sync(0xffffffffu, rm, off, 16));
            float mn   = fmaxf(m[i], rm);
            float corr = __expf(m[i] - mn);
            m[i] = mn;
            float rs = 0.f;
            #pragma unroll
            for (int j = 0; j < 4; ++j) {
                float p = __expf(s[i][j] - mn);
                s[i][j] = p;
                rs += p;
            }
            #pragma unroll
            for (int off = 8; off > 0; off >>= 1)
                rs += __shfl_xor_sync(0xffffffffu, rs, off, 16);
            l[i] = l[i] * corr + rs;
            #pragma unroll
            for (int j = 0; j < 4; ++j) o[i][j] *= corr;
        }

        // Stage P to smem for the PV GEMM (padded stride: conflict-free reads).
        #pragma unroll
        for (int i = 0; i < 4; ++i) {
            float4 p4 = make_float4(s[i][0], s[i][1], s[i][2], s[i][3]);
            *(float4*)&Ps[(ty*4 + i)*PSTR + tx*4] = p4;
        }
        __syncthreads();

        // O += P V  (64x64x64)
        #pragma unroll 2
        for (int c = 0; c < 64; c += 4) {
            float p[4][4];
            #pragma unroll
            for (int i = 0; i < 4; ++i) {
                float4 t4 = *(const float4*)&Ps[(ty*4 + i)*PSTR + c];
                p[i][0] = t4.x; p[i][1] = t4.y; p[i][2] = t4.z; p[i][3] = t4.w;
            }
            #pragma unroll
            for (int jj = 0; jj < 4; ++jj) {
                float4 vv = *(const float4*)&Vs[(c + jj)*64 + tx*4];
                float vr[4] = {vv.x, vv.y, vv.z, vv.w};
                #pragma unroll
                for (int i = 0; i < 4; ++i)
                    #pragma unroll
                    for (int j = 0; j < 4; ++j)
                        o[i][j] = fmaf(p[i][jj], vr[j], o[i][j]);
            }
        }
    }

    // Epilogue: normalize and store.
    float* ob = Og + (size_t)b * oOffB + (size_t)h * oOffH;
    #pragma unroll
    for (int i = 0; i < 4; ++i) {
        float inv = 1.f / l[i];
        float4 r4 = make_float4(o[i][0]*inv, o[i][1]*inv, o[i][2]*inv, o[i][3]*inv);
        *(float4*)&ob[(size_t)(q0 + ty*4 + i) * oRS + tx*4] = r4;
    }
}

// ---------------------------------------------------------------------------

extern "C" void kernel_launch(void* const* d_in, const int* in_sizes, int n_in,
                              void* d_out, int out_size)
{
    const float* x   = (const float*)d_in[0];
    const float* x2  = (const float*)d_in[1];
    const float* Wq  = (const float*)d_in[2];
    const float* Wa  = (const float*)d_in[3];
    const float* Wkv = (const float*)d_in[4];
    float* out = (float*)d_out;

    float *q, *a, *k, *v, *t;
    cudaGetSymbolAddress((void**)&q, g_q);
    cudaGetSymbolAddress((void**)&a, g_a);
    cudaGetSymbolAddress((void**)&k, g_k);
    cudaGetSymbolAddress((void**)&v, g_v);
    cudaGetSymbolAddress((void**)&t, g_t);

    const int SMEM_BYTES = (3*64*PSTR + 64*64) * 4;   // 68608 B
    cudaFuncSetAttribute(flash_kernel,
                         cudaFuncAttributeMaxDynamicSharedMemorySize, SMEM_BYTES);

    dim3 blk(256);

    // Projections (head-scattered outputs)
    proj_kernel<<<dim3(16, 64), blk>>>(x,  Wq,  q, nullptr, 0);
    proj_kernel<<<dim3(32, 64), blk>>>(x,  Wkv, k, v,       1);
    proj_kernel<<<dim3(16, 64), blk>>>(x2, Wa,  a, nullptr, 0);

    // Pass 1: tmp = softmax(A k^T * s) v   (head layout out)
    flash_kernel<<<dim3(NSEQ/64, NB*NH), blk, SMEM_BYTES>>>(
        a, k, v, t,
        (long long)NH * NSEQ * ND, (long long)NSEQ * ND, ND);

    // Pass 2: out = softmax(q A^T * s) tmp  (written directly as [B,N,C])
    flash_kernel<<<dim3(NSEQ/64, NB*NH), blk, SMEM_BYTES>>>(
        q, a, t, out,
        (long long)NSEQ * NC, (long long)ND, NC);
}

// round 17
// speedup vs baseline: 1.1048x; 1.1048x over previous
#include <cuda_runtime.h>

#define NB 2
#define NSEQ 2048
#define NC 1024
#define NH 16
#define ND 64
#define ATT_SCALE 0.125f

// Scratch (device globals: the sanctioned alloc-free workaround). 5 x 16.8 MB.
__device__ float g_q[NB*NH*NSEQ*ND];
__device__ float g_a[NB*NH*NSEQ*ND];
__device__ float g_k[NB*NH*NSEQ*ND];
__device__ float g_v[NB*NH*NSEQ*ND];
__device__ float g_t[NB*NH*NSEQ*ND];

// ---------------------------------------------------------------------------
// Projection GEMM: O = X[4096 x 1024] @ W^T, 128x128 CTA tile, 8x8 per thread.
// Epilogue scatters into head layout [B,H,N,D]; each 64-col group maps to one
// head (64-aligned). kvMode==1: cols [0,1024)->O0 (k), [1024,2048)->O1 (v).
// ---------------------------------------------------------------------------
__global__ __launch_bounds__(256, 2) void proj_kernel(
    const float* __restrict__ X, const float* __restrict__ W,
    float* __restrict__ O0, float* __restrict__ O1, int kvMode)
{
    __shared__ float As[16][132];   // k-major: As[k][row]
    __shared__ float Bs[16][132];   // k-major: Bs[k][col]

    const int tid = threadIdx.x;
    const int tx  = tid & 15;
    const int ty  = tid >> 4;
    const int col0 = blockIdx.x * 128;
    const int row0 = blockIdx.y * 128;

    const int rw = tid >> 1;          // 0..127
    const int kg = (tid & 1) * 8;     // 0 or 8
    const float* Xr = X + (size_t)(row0 + rw) * NC + kg;
    const float* Wr = W + (size_t)(col0 + rw) * NC + kg;

    float acc[8][8] = {};

    for (int kt = 0; kt < NC; kt += 16) {
        float4 xa = *(const float4*)(Xr + kt);
        float4 xb = *(const float4*)(Xr + kt + 4);
        float4 wa = *(const float4*)(Wr + kt);
        float4 wb = *(const float4*)(Wr + kt + 4);
        __syncthreads();   // previous tile's compute done
        As[kg+0][rw] = xa.x; As[kg+1][rw] = xa.y;
        As[kg+2][rw] = xa.z; As[kg+3][rw] = xa.w;
        As[kg+4][rw] = xb.x; As[kg+5][rw] = xb.y;
        As[kg+6][rw] = xb.z; As[kg+7][rw] = xb.w;
        Bs[kg+0][rw] = wa.x; Bs[kg+1][rw] = wa.y;
        Bs[kg+2][rw] = wa.z; Bs[kg+3][rw] = wa.w;
        Bs[kg+4][rw] = wb.x; Bs[kg+5][rw] = wb.y;
        Bs[kg+6][rw] = wb.z; Bs[kg+7][rw] = wb.w;
        __syncthreads();

        #pragma unroll
        for (int kk = 0; kk < 16; ++kk) {
            float4 a0 = *(const float4*)&As[kk][ty*4];
            float4 a1 = *(const float4*)&As[kk][64 + ty*4];
            float4 b0 = *(const float4*)&Bs[kk][tx*4];
            float4 b1 = *(const float4*)&Bs[kk][64 + tx*4];
            float ar[8] = {a0.x,a0.y,a0.z,a0.w, a1.x,a1.y,a1.z,a1.w};
            float br[8] = {b0.x,b0.y,b0.z,b0.w, b1.x,b1.y,b1.z,b1.w};
            #pragma unroll
            for (int i = 0; i < 8; ++i)
                #pragma unroll
                for (int j = 0; j < 8; ++j)
                    acc[i][j] = fmaf(ar[i], br[j], acc[i][j]);
        }
    }

    const int b  = row0 >> 11;          // row0 / NSEQ
    const int n0 = row0 & (NSEQ - 1);

    #pragma unroll
    for (int cg = 0; cg < 2; ++cg) {
        const int colb = col0 + cg * 64;     // 64-aligned -> single head
        float* dst;
        int hh;
        if (!kvMode) { dst = O0; hh = colb >> 6; }
        else {
            int s = colb >> 10;              // 0 -> k, 1 -> v
            hh = (colb >> 6) & (NH - 1);
            dst = s ? O1 : O0;
        }
        float* ob = dst + ((size_t)(b*NH + hh) * NSEQ + n0) * ND;
        #pragma unroll
        for (int rg = 0; rg < 2; ++rg) {
            #pragma unroll
            for (int i = 0; i < 4; ++i) {
                int r = rg*64 + ty*4 + i;
                float4 r4 = make_float4(acc[rg*4+i][cg*4+0], acc[rg*4+i][cg*4+1],
                                        acc[rg*4+i][cg*4+2], acc[rg*4+i][cg*4+3]);
                *(float4*)&ob[(size_t)r * ND + tx*4] = r4;
            }
        }
    }
}

// ---------------------------------------------------------------------------
// Flash attention (fp32, online softmax). Br=128 queries x Bc=64 keys per
// CTA tile, 256 threads, per-thread 8 rows x 4 cols (two row groups at
// ty*4 and 64+ty*4). D=64. Output addressing generic (oOffB/oOffH/oRS) so
// pass 2 writes straight into [B,N,C].
// __launch_bounds__(256,2): pin regs <= 128 so 2 CTAs/SM is guaranteed
// (smem 100KB also fits 2x in 228KB).
// ---------------------------------------------------------------------------
__global__ __launch_bounds__(256, 2) void flash_kernel(
    const float* __restrict__ Qg, const float* __restrict__ Kg,
    const float* __restrict__ Vg, float* __restrict__ Og,
    long long oOffB, long long oOffH, int oRS)
{
    extern __shared__ float sm[];
    float* Qt = sm;                   // [64][132]  d-major: Qt[d*132 + r], r<128
    float* Kt = Qt + 64*132;          // [64][68]   d-major: Kt[d*68 + c],  c<64
    float* Vs = Kt + 64*68;           // [64][64]   c-major: Vs[c*64 + dcol]
    float* Ps = Vs + 64*64;           // [128][68]  r-major: Ps[r*68 + c]

    const int tid = threadIdx.x;
    const int tx  = tid & 15;
    const int ty  = tid >> 4;
    const int bh  = blockIdx.y;
    const int b   = bh >> 4;
    const int h   = bh & (NH - 1);
    const int q0  = blockIdx.x * 128;

    const float* Qb = Qg + (size_t)bh * NSEQ * ND + (size_t)q0 * ND;
    const float* Kb = Kg + (size_t)bh * NSEQ * ND;
    const float* Vb = Vg + (size_t)bh * NSEQ * ND;

    // Load Q tile (128x64) transposed to d-major. 2048 float4, 8 per thread.
    #pragma unroll
    for (int it = 0; it < 8; ++it) {
        int idx = tid + it * 256;
        int n  = idx >> 4;            // 0..127
        int dg = (idx & 15) << 2;
        float4 v4 = *(const float4*)(Qb + (size_t)n * ND + dg);
        Qt[(dg+0)*132 + n] = v4.x; Qt[(dg+1)*132 + n] = v4.y;
        Qt[(dg+2)*132 + n] = v4.z; Qt[(dg+3)*132 + n] = v4.w;
    }

    float o[8][4] = {};
    float m[8], l[8];
    #pragma unroll
    for (int i = 0; i < 8; ++i) { m[i] = -1e30f; l[i] = 0.f; }

    for (int kt0 = 0; kt0 < NSEQ; kt0 += 64) {
        __syncthreads();   // prev PV done (iter 0: Q stores covered)

        // Load K (d-major) and V (c-major) 64x64 tiles: 4 float4 each/thread.
        #pragma unroll
        for (int it = 0; it < 4; ++it) {
            int idx = tid + it * 256;
            int n  = idx >> 4;        // 0..63
            int dg = (idx & 15) << 2;
            float4 k4 = *(const float4*)(Kb + (size_t)(kt0 + n) * ND + dg);
            Kt[(dg+0)*68 + n] = k4.x; Kt[(dg+1)*68 + n] = k4.y;
            Kt[(dg+2)*68 + n] = k4.z; Kt[(dg+3)*68 + n] = k4.w;
            float4 v4 = *(const float4*)(Vb + (size_t)(kt0 + n) * ND + dg);
            *(float4*)&Vs[n*64 + dg] = v4;
        }
        __syncthreads();

        // S = Q K^T : per thread 8 rows x 4 cols, rank-1 over d.
        float s[8][4] = {};
        #pragma unroll 4
        for (int d = 0; d < 64; ++d) {
            float4 qa = *(const float4*)&Qt[d*132 + ty*4];
            float4 qb = *(const float4*)&Qt[d*132 + 64 + ty*4];
            float4 kv = *(const float4*)&Kt[d*68 + tx*4];
            float qr[8] = {qa.x,qa.y,qa.z,qa.w, qb.x,qb.y,qb.z,qb.w};
            float kr[4] = {kv.x,kv.y,kv.z,kv.w};
            #pragma unroll
            for (int i = 0; i < 8; ++i)
                #pragma unroll
                for (int j = 0; j < 4; ++j)
                    s[i][j] = fmaf(qr[i], kr[j], s[i][j]);
        }

        // Online softmax (row reductions across 16 tx lanes).
        #pragma unroll
        for (int i = 0; i < 8; ++i) {
            #pragma unroll
            for (int j = 0; j < 4; ++j) s[i][j] *= ATT_SCALE;
            float rm = fmaxf(fmaxf(s[i][0], s[i][1]), fmaxf(s[i][2], s[i][3]));
            #pragma unroll
            for (int off = 8; off > 0; off >>= 1)
                rm = fmaxf(rm, __shfl_xor_sync(0xffffffffu, rm, off, 16));
            float mn   = fmaxf(m[i], rm);
            float corr = __expf(m[i] - mn);
            m[i] = mn;
            float rs = 0.f;
            #pragma unroll
            for (int j = 0; j < 4; ++j) {
                float p = __expf(s[i][j] - mn);
                s[i][j] = p;
                rs += p;
            }
            #pragma unroll
            for (int off = 8; off > 0; off >>= 1)
                rs += __shfl_xor_sync(0xffffffffu, rs, off, 16);
            l[i] = l[i] * corr + rs;
            #pragma unroll
            for (int j = 0; j < 4; ++j) o[i][j] *= corr;
        }

        // Stage P to smem (padded stride 68: conflict-free reads).
        #pragma unroll
        for (int i = 0; i < 8; ++i) {
            int r = (i < 4) ? (ty*4 + i) : (64 + ty*4 + (i - 4));
            float4 p4 = make_float4(s[i][0], s[i][1], s[i][2], s[i][3]);
            *(float4*)&Ps[r*68 + tx*4] = p4;
        }
        __syncthreads();

        // O += P V : per c-step, 12 LDS.128 -> 128 FMA per thread.
        #pragma unroll 2
        for (int c = 0; c < 64; c += 4) {
            float p[8][4];
            #pragma unroll
            for (int i = 0; i < 8; ++i) {
                int r = (i < 4) ? (ty*4 + i) : (64 + ty*4 + (i - 4));
                float4 t4 = *(const float4*)&Ps[r*68 + c];
                p[i][0] = t4.x; p[i][1] = t4.y; p[i][2] = t4.z; p[i][3] = t4.w;
            }
            #pragma unroll
            for (int jj = 0; jj < 4; ++jj) {
                float4 vv = *(const float4*)&Vs[(c + jj)*64 + tx*4];
                float vr[4] = {vv.x, vv.y, vv.z, vv.w};
                #pragma unroll
                for (int i = 0; i < 8; ++i)
                    #pragma unroll
                    for (int j = 0; j < 4; ++j)
                        o[i][j] = fmaf(p[i][jj], vr[j], o[i][j]);
            }
        }
    }

    // Epilogue: normalize and store.
    float* ob = Og + (size_t)b * oOffB + (size_t)h * oOffH;
    #pragma unroll
    for (int i = 0; i < 8; ++i) {
        int r = (i < 4) ? (ty*4 + i) : (64 + ty*4 + (i - 4));
        float inv = 1.f / l[i];
        float4 r4 = make_float4(o[i][0]*inv, o[i][1]*inv, o[i][2]*inv, o[i][3]*inv);
        *(float4*)&ob[(size_t)(q0 + r) * oRS + tx*4] = r4;
    }
}

// ---------------------------------------------------------------------------

extern "C" void kernel_launch(void* const* d_in, const int* in_sizes, int n_in,
                              void* d_out, int out_size)
{
    const float* x   = (const float*)d_in[0];
    const float* x2  = (const float*)d_in[1];
    const float* Wq  = (const float*)d_in[2];
    const float* Wa  = (const float*)d_in[3];
    const float* Wkv = (const float*)d_in[4];
    float* out = (float*)d_out;

    float *q, *a, *k, *v, *t;
    cudaGetSymbolAddress((void**)&q, g_q);
    cudaGetSymbolAddress((void**)&a, g_a);
    cudaGetSymbolAddress((void**)&k, g_k);
    cudaGetSymbolAddress((void**)&v, g_v);
    cudaGetSymbolAddress((void**)&t, g_t);

    const int SMEM_BYTES = (64*132 + 64*68 + 64*64 + 128*68) * 4;   // 102400 B
    cudaFuncSetAttribute(flash_kernel,
                         cudaFuncAttributeMaxDynamicSharedMemorySize, SMEM_BYTES);

    dim3 blk(256);

    // Projections (head-scattered outputs), 128x128 tiles
    proj_kernel<<<dim3( 8, 32), blk>>>(x,  Wq,  q, nullptr, 0);
    proj_kernel<<<dim3(16, 32), blk>>>(x,  Wkv, k, v,       1);
    proj_kernel<<<dim3( 8, 32), blk>>>(x2, Wa,  a, nullptr, 0);

    // Pass 1: tmp = softmax(A k^T * s) v   (head layout out)
    flash_kernel<<<dim3(NSEQ/128, NB*NH), blk, SMEM_BYTES>>>(
        a, k, v, t,
        (long long)NH * NSEQ * ND, (long long)NSEQ * ND, ND);

    // Pass 2: out = softmax(q A^T * s) tmp  (written directly as [B,N,C])
    flash_kernel<<<dim3(NSEQ/128, NB*NH), blk, SMEM_BYTES>>>(
        q, a, t, out,
        (long long)NSEQ * NC, (long long)ND, NC);
}